// round 6
// baseline (speedup 1.0000x reference)
#include <cuda_runtime.h>
#include <cuda_fp16.h>
#include <cstdint>

// Problem constants
#define Hh   16
#define Ss   1024
#define Dd   1024
#define HDd  64
#define Bb   8
#define BHh  (Bb*Hh)      // 128
#define Mtot (Bb*Ss)      // 8192

// fp16 scratch (device globals; no allocation allowed)
__device__ __half g_X16[(size_t)Mtot*Dd];
__device__ __half g_W16[(size_t)3*Dd*Dd];
__device__ __half g_M16[(size_t)Bb*Ss*Ss];         // fp16 mask (0/1 exact)
__device__ __half g_Q16[(size_t)BHh*Ss*HDd];       // head-major, pre-scaled by log2e/8
__device__ __half g_K16[(size_t)BHh*Ss*HDd];
__device__ __half g_V16[(size_t)BHh*Ss*HDd];

// ---------------------------------------------------------------------------
__device__ __forceinline__ uint32_t h2u(__half2 h) {
    union { __half2 h; uint32_t u; } c; c.h = h; return c.u;
}
__device__ __forceinline__ float ex2f(float x) {
    float y; asm("ex2.approx.f32 %0, %1;" : "=f"(y) : "f"(x)); return y;
}
__device__ __forceinline__ uint32_t smem_u32(const void* p) {
    uint32_t a;
    asm("{ .reg .u64 t; cvta.to.shared.u64 t, %1; cvt.u32.u64 %0, t; }" : "=r"(a) : "l"(p));
    return a;
}
#define CP_ASYNC(dst, src) \
    asm volatile("cp.async.ca.shared.global [%0], [%1], 16;" :: "r"(dst), "l"(src) : "memory")
#define CP_COMMIT() asm volatile("cp.async.commit_group;" ::: "memory")
#define CP_WAIT(n)  asm volatile("cp.async.wait_group %0;" :: "n"(n) : "memory")

__device__ __forceinline__ void ldsm_x4(uint32_t* r, uint32_t addr) {
    asm volatile("ldmatrix.sync.aligned.m8n8.x4.shared.b16 {%0,%1,%2,%3}, [%4];"
                 : "=r"(r[0]), "=r"(r[1]), "=r"(r[2]), "=r"(r[3]) : "r"(addr));
}
__device__ __forceinline__ void ldsm_x4_t(uint32_t* r, uint32_t addr) {
    asm volatile("ldmatrix.sync.aligned.m8n8.x4.trans.shared.b16 {%0,%1,%2,%3}, [%4];"
                 : "=r"(r[0]), "=r"(r[1]), "=r"(r[2]), "=r"(r[3]) : "r"(addr));
}
__device__ __forceinline__ void ldsm_x2_t(uint32_t* r, uint32_t addr) {
    asm volatile("ldmatrix.sync.aligned.m8n8.x2.trans.shared.b16 {%0,%1}, [%2];"
                 : "=r"(r[0]), "=r"(r[1]) : "r"(addr));
}
__device__ __forceinline__ void mma16(float* c, const uint32_t* a, uint32_t b0, uint32_t b1) {
    asm volatile(
        "mma.sync.aligned.m16n8k16.row.col.f32.f16.f16.f32 "
        "{%0,%1,%2,%3}, {%4,%5,%6,%7}, {%8,%9}, {%0,%1,%2,%3};"
        : "+f"(c[0]), "+f"(c[1]), "+f"(c[2]), "+f"(c[3])
        : "r"(a[0]), "r"(a[1]), "r"(a[2]), "r"(a[3]), "r"(b0), "r"(b1));
}
__device__ __forceinline__ uint32_t ldsm_addr(uint32_t base, int r0, int c0b,
                                              int rowb, int lane) {
    return base + (uint32_t)(r0 + (lane & 15)) * rowb + c0b + ((lane >> 4) << 4);
}

// ---------------------------------------------------------------------------
__global__ void conv_fp16(const float4* __restrict__ src, __half2* __restrict__ dst, int n4)
{
    int i = blockIdx.x * blockDim.x + threadIdx.x;
    if (i < n4) {
        float4 v = src[i];
        dst[2*i]   = __floats2half2_rn(v.x, v.y);
        dst[2*i+1] = __floats2half2_rn(v.z, v.w);
    }
}

// ---------------------------------------------------------------------------
// Projection GEMM, fp16 HMMA, occupancy 2. Q output pre-scaled by log2e/8.
// ---------------------------------------------------------------------------
#define PA_ROWB 144
#define PB_ROWB 272
#define PA_STAGE 18432
#define PB_STAGE 17408
#define PROJ_SMEM (2*PA_STAGE + 2*PB_STAGE)   // 71680

__global__ __launch_bounds__(256, 2) void proj16_kernel()
{
    extern __shared__ char sm[];
    const uint32_t sb = smem_u32(sm);
    const uint32_t Ab = sb, Bb_ = sb + 2*PA_STAGE;

    const int tid = threadIdx.x, wid = tid >> 5, lane = tid & 31;
    const int g = lane >> 2, tig = lane & 3;
    const int wm = wid & 3, wn = wid >> 2;

    const int z  = blockIdx.z;
    const int n0 = blockIdx.x * 128;
    const int m0 = blockIdx.y * 128;
    const __half* Xp = g_X16 + (size_t)m0 * Dd;
    const __half* Wp = g_W16 + (size_t)z * Dd * Dd + n0;
    __half* Out = (z == 0) ? g_Q16 : (z == 1 ? g_K16 : g_V16);
    const float osc = (z == 0) ? 0.18033688f : 1.0f;   // log2(e)/8 folded into Q

    float C[2][8][4];
    #pragma unroll
    for (int mf = 0; mf < 2; mf++)
        #pragma unroll
        for (int nf = 0; nf < 8; nf++)
            #pragma unroll
            for (int r = 0; r < 4; r++) C[mf][nf][r] = 0.f;

    auto stage = [&](int kt, int buf) {
        const int k0 = kt * 64;
        #pragma unroll
        for (int i = 0; i < 4; i++) {
            int ci = tid + 256 * i;
            int row = ci >> 3, seg = ci & 7;
            CP_ASYNC(Ab + buf * PA_STAGE + row * PA_ROWB + seg * 16,
                     Xp + (size_t)row * Dd + k0 + seg * 8);
        }
        #pragma unroll
        for (int i = 0; i < 4; i++) {
            int ci = tid + 256 * i;
            int row = ci >> 4, seg = ci & 15;
            CP_ASYNC(Bb_ + buf * PB_STAGE + row * PB_ROWB + seg * 16,
                     Wp + (size_t)(k0 + row) * Dd + seg * 8);
        }
        CP_COMMIT();
    };

    stage(0, 0);
    for (int kt = 0; kt < 16; kt++) {
        if (kt < 15) { stage(kt + 1, (kt + 1) & 1); CP_WAIT(1); }
        else         { CP_WAIT(0); }
        __syncthreads();

        const uint32_t ab = Ab + (kt & 1) * PA_STAGE;
        const uint32_t bbuf = Bb_ + (kt & 1) * PB_STAGE;
        #pragma unroll
        for (int k16 = 0; k16 < 4; k16++) {
            uint32_t a[2][4];
            #pragma unroll
            for (int mf = 0; mf < 2; mf++)
                ldsm_x4(a[mf], ldsm_addr(ab, wm * 32 + mf * 16, k16 * 32, PA_ROWB, lane));
            #pragma unroll
            for (int nfp = 0; nfp < 4; nfp++) {
                uint32_t r[4];
                ldsm_x4_t(r, ldsm_addr(bbuf, k16 * 16, (wn * 64 + nfp * 16) * 2, PB_ROWB, lane));
                #pragma unroll
                for (int mf = 0; mf < 2; mf++) {
                    mma16(C[mf][2*nfp],     a[mf], r[0], r[1]);
                    mma16(C[mf][2*nfp + 1], a[mf], r[2], r[3]);
                }
            }
        }
        __syncthreads();
    }

    const int h = (n0 >> 6) + wn;
    #pragma unroll
    for (int mf = 0; mf < 2; mf++) {
        int m = m0 + wm * 32 + mf * 16 + g;
        int bidx = m >> 10, s = m & 1023;
        __half* base  = Out + ((size_t)(bidx * Hh + h) * Ss + s) * HDd;
        __half* base2 = base + 8 * HDd;
        #pragma unroll
        for (int nf = 0; nf < 8; nf++) {
            int d = nf * 8 + 2 * tig;
            *(__half2*)(base + d)  = __floats2half2_rn(C[mf][nf][0]*osc, C[mf][nf][1]*osc);
            *(__half2*)(base2 + d) = __floats2half2_rn(C[mf][nf][2]*osc, C[mf][nf][3]*osc);
        }
    }
}

// ---------------------------------------------------------------------------
// Attention, fp16 HMMA, occupancy 2. No Q smem (LDG fragments).
// Per 16-col chunk: S-mma -> ex2 -> fp16-mask -> PV-mma (+ones-column rowsum).
// ---------------------------------------------------------------------------
#define A_ROWB 144                 // 72 halves: 64 data + col64=1.0 (V) + pad
#define AKV_BYTES (64*A_ROWB)      // 9216
#define ATTN_SMEM (4*AKV_BYTES)    // 36864 (K x2 bufs, V x2 bufs)

__global__ __launch_bounds__(256, 2) void attn16_kernel(float* __restrict__ out)
{
    extern __shared__ char sm[];
    const uint32_t sb = smem_u32(sm);
    const uint32_t Kb = sb, Vb = sb + 2*AKV_BYTES;

    const int tid = threadIdx.x, w = tid >> 5, lane = tid & 31;
    const int g = lane >> 2, tig = lane & 3;
    const int bh = blockIdx.y, b = bh >> 4, h = bh & 15;
    const int q0 = blockIdx.x * 256;
    const int i0 = w * 32;

    const __half* Qg = g_Q16 + (size_t)bh * Ss * HDd + (size_t)q0 * HDd;
    const __half* Kg = g_K16 + (size_t)bh * Ss * HDd;
    const __half* Vg = g_V16 + (size_t)bh * Ss * HDd;
    const __half* mb16 = g_M16 + ((size_t)b * Ss + q0 + i0) * Ss;

    auto stageKV = [&](int t0, int buf) {
        #pragma unroll
        for (int i = 0; i < 2; i++) {
            int ci = tid + 256 * i;
            int row = ci >> 3, seg = ci & 7;
            CP_ASYNC(Kb + buf * AKV_BYTES + row * A_ROWB + seg * 16,
                     Kg + (size_t)(t0 + row) * HDd + seg * 8);
        }
        #pragma unroll
        for (int i = 0; i < 2; i++) {
            int ci = tid + 256 * i;
            int row = ci >> 3, seg = ci & 7;
            CP_ASYNC(Vb + buf * AKV_BYTES + row * A_ROWB + seg * 16,
                     Vg + (size_t)(t0 + row) * HDd + seg * 8);
        }
        CP_COMMIT();
    };

    // ones-column tail for V (col 64 = 1.0, cols 65-71 = 0); never overwritten
    if (tid < 128) {
        int buf = tid >> 6, row = tid & 63;
        uint4 tail = make_uint4(0x00003C00u, 0u, 0u, 0u);
        *(uint4*)(sm + 2*AKV_BYTES + buf * AKV_BYTES + row * A_ROWB + 128) = tail;
    }

    // Q fragments straight from global (pre-scaled by log2e/8 in proj)
    uint32_t qf[2][4][4];
    #pragma unroll
    for (int mf = 0; mf < 2; mf++) {
        const __half* r0 = Qg + (size_t)(i0 + mf * 16 + g) * HDd;
        const __half* r1 = r0 + 8 * HDd;
        #pragma unroll
        for (int k16 = 0; k16 < 4; k16++) {
            qf[mf][k16][0] = *(const uint32_t*)(r0 + k16 * 16 + 2 * tig);
            qf[mf][k16][1] = *(const uint32_t*)(r1 + k16 * 16 + 2 * tig);
            qf[mf][k16][2] = *(const uint32_t*)(r0 + k16 * 16 + 8 + 2 * tig);
            qf[mf][k16][3] = *(const uint32_t*)(r1 + k16 * 16 + 8 + 2 * tig);
        }
    }

    stageKV(0, 0);

    float O[2][8][4];
    float O9[2][4];
    #pragma unroll
    for (int mf = 0; mf < 2; mf++) {
        #pragma unroll
        for (int nf = 0; nf < 8; nf++)
            #pragma unroll
            for (int r = 0; r < 4; r++) O[mf][nf][r] = 0.f;
        #pragma unroll
        for (int r = 0; r < 4; r++) O9[mf][r] = 0.f;
    }

    for (int t = 0; t < 16; t++) {
        const int t0 = t * 64, buf = t & 1;
        if (t < 15) { stageKV(t0 + 64, buf ^ 1); CP_WAIT(1); }
        else        { CP_WAIT(0); }
        __syncthreads();

        const uint32_t kb = Kb + buf * AKV_BYTES;
        const uint32_t vb = Vb + buf * AKV_BYTES;

        #pragma unroll
        for (int kt = 0; kt < 4; kt++) {
            // S chunk: 32 q-rows x 16 t-cols
            float S[2][2][4];
            #pragma unroll
            for (int mf = 0; mf < 2; mf++)
                #pragma unroll
                for (int n2 = 0; n2 < 2; n2++)
                    #pragma unroll
                    for (int r = 0; r < 4; r++) S[mf][n2][r] = 0.f;
            #pragma unroll
            for (int k16 = 0; k16 < 4; k16++) {
                uint32_t kr[4];
                ldsm_x4(kr, ldsm_addr(kb, kt * 16, k16 * 32, A_ROWB, lane));
                #pragma unroll
                for (int mf = 0; mf < 2; mf++) {
                    mma16(S[mf][0], qf[mf][k16], kr[0], kr[2]);
                    mma16(S[mf][1], qf[mf][k16], kr[1], kr[3]);
                }
            }

            // P = ex2(S) * mask (fp16, binary mask exact)
            uint32_t Pp[2][2][2];
            #pragma unroll
            for (int mf = 0; mf < 2; mf++) {
                #pragma unroll
                for (int n2 = 0; n2 < 2; n2++) {
                    const __half* mp = mb16 + (size_t)(mf * 16 + g) * Ss
                                       + t0 + (kt * 2 + n2) * 8 + 2 * tig;
                    __half2 m01 = *(const __half2*)mp;
                    __half2 m23 = *(const __half2*)(mp + 8 * Ss);
                    float e0 = ex2f(S[mf][n2][0]);
                    float e1 = ex2f(S[mf][n2][1]);
                    float e2 = ex2f(S[mf][n2][2]);
                    float e3 = ex2f(S[mf][n2][3]);
                    Pp[mf][n2][0] = h2u(__hmul2(__floats2half2_rn(e0, e1), m01));
                    Pp[mf][n2][1] = h2u(__hmul2(__floats2half2_rn(e2, e3), m23));
                }
            }

            // O += P V  (this 16-row chunk of V)
            #pragma unroll
            for (int nfp = 0; nfp < 4; nfp++) {
                uint32_t vr[4];
                ldsm_x4_t(vr, ldsm_addr(vb, kt * 16, nfp * 32, A_ROWB, lane));
                #pragma unroll
                for (int mf = 0; mf < 2; mf++) {
                    uint32_t a[4] = { Pp[mf][0][0], Pp[mf][0][1],
                                      Pp[mf][1][0], Pp[mf][1][1] };
                    mma16(O[mf][2*nfp],     a, vr[0], vr[1]);
                    mma16(O[mf][2*nfp + 1], a, vr[2], vr[3]);
                }
            }
            // ones-column: row sums via tensor core
            {
                uint32_t orr[2];
                ldsm_x2_t(orr, vb + (uint32_t)(kt * 16 + (lane & 15)) * A_ROWB + 128);
                #pragma unroll
                for (int mf = 0; mf < 2; mf++) {
                    uint32_t a[4] = { Pp[mf][0][0], Pp[mf][0][1],
                                      Pp[mf][1][0], Pp[mf][1][1] };
                    mma16(O9[mf], a, orr[0], orr[1]);
                }
            }
        }
        __syncthreads();
    }

    // normalize + store (rowsum lives in lane tig=0, col 64)
    #pragma unroll
    for (int mf = 0; mf < 2; mf++) {
        float r0 = __shfl_sync(0xffffffffu, O9[mf][0], lane & ~3);
        float r1 = __shfl_sync(0xffffffffu, O9[mf][2], lane & ~3);
        const float inv0 = 1.0f / (r0 + 1e-8f);
        const float inv1 = 1.0f / (r1 + 1e-8f);
        float* o0 = out + ((size_t)b * Ss + q0 + i0 + mf * 16 + g) * Dd + h * HDd;
        float* o1 = o0 + 8 * Dd;
        #pragma unroll
        for (int nf = 0; nf < 8; nf++) {
            int d = nf * 8 + 2 * tig;
            *(float2*)(o0 + d) = make_float2(O[mf][nf][0] * inv0, O[mf][nf][1] * inv0);
            *(float2*)(o1 + d) = make_float2(O[mf][nf][2] * inv1, O[mf][nf][3] * inv1);
        }
    }
}

// ---------------------------------------------------------------------------
extern "C" void kernel_launch(void* const* d_in, const int* in_sizes, int n_in,
                              void* d_out, int out_size)
{
    const float* x    = (const float*)d_in[0];
    const float* mask = (const float*)d_in[1];
    const float* Wq   = (const float*)d_in[2];
    const float* Wk   = (const float*)d_in[3];
    const float* Wv   = (const float*)d_in[4];
    float* out = (float*)d_out;

    __half* gX; cudaGetSymbolAddress((void**)&gX, g_X16);
    __half* gW; cudaGetSymbolAddress((void**)&gW, g_W16);
    __half* gM; cudaGetSymbolAddress((void**)&gM, g_M16);

    const int n4x = Mtot * Dd / 4;
    const int n4w = Dd * Dd / 4;
    const int n4m = Bb * Ss * Ss / 4;
    conv_fp16<<<(n4x + 255) / 256, 256>>>((const float4*)x, (__half2*)gX, n4x);
    conv_fp16<<<(n4w + 255) / 256, 256>>>((const float4*)Wq, (__half2*)gW, n4w);
    conv_fp16<<<(n4w + 255) / 256, 256>>>((const float4*)Wk, (__half2*)(gW + (size_t)Dd*Dd), n4w);
    conv_fp16<<<(n4w + 255) / 256, 256>>>((const float4*)Wv, (__half2*)(gW + (size_t)2*Dd*Dd), n4w);
    conv_fp16<<<(n4m + 255) / 256, 256>>>((const float4*)mask, (__half2*)gM, n4m);

    cudaFuncSetAttribute(proj16_kernel, cudaFuncAttributeMaxDynamicSharedMemorySize,
                         PROJ_SMEM);
    dim3 pgrid(Dd / 128, Mtot / 128, 3);
    proj16_kernel<<<pgrid, 256, PROJ_SMEM>>>();

    cudaFuncSetAttribute(attn16_kernel, cudaFuncAttributeMaxDynamicSharedMemorySize,
                         ATTN_SMEM);
    dim3 agrid(Ss / 256, BHh);
    attn16_kernel<<<agrid, 256, ATTN_SMEM>>>(out);
}

// round 7
// speedup vs baseline: 1.1630x; 1.1630x over previous
#include <cuda_runtime.h>
#include <cuda_fp16.h>
#include <cstdint>

// Problem constants
#define Hh   16
#define Ss   1024
#define Dd   1024
#define HDd  64
#define Bb   8
#define BHh  (Bb*Hh)      // 128
#define Mtot (Bb*Ss)      // 8192

// fp16 scratch (device globals; no allocation allowed)
__device__ __half g_X16[(size_t)Mtot*Dd];
__device__ __half g_W16[(size_t)3*Dd*Dd];
__device__ __half g_M16[(size_t)Bb*Ss*Ss];         // fp16 mask (0/1 exact)
__device__ __half g_Q16[(size_t)BHh*Ss*HDd];       // head-major, pre-scaled by log2e/8
__device__ __half g_K16[(size_t)BHh*Ss*HDd];
__device__ __half g_V16[(size_t)BHh*Ss*HDd];

// ---------------------------------------------------------------------------
__device__ __forceinline__ uint32_t h2u(__half2 h) {
    union { __half2 h; uint32_t u; } c; c.h = h; return c.u;
}
__device__ __forceinline__ float ex2f(float x) {
    float y; asm("ex2.approx.f32 %0, %1;" : "=f"(y) : "f"(x)); return y;
}
__device__ __forceinline__ uint32_t smem_u32(const void* p) {
    uint32_t a;
    asm("{ .reg .u64 t; cvta.to.shared.u64 t, %1; cvt.u32.u64 %0, t; }" : "=r"(a) : "l"(p));
    return a;
}
#define CP_ASYNC(dst, src) \
    asm volatile("cp.async.ca.shared.global [%0], [%1], 16;" :: "r"(dst), "l"(src) : "memory")
#define CP_COMMIT() asm volatile("cp.async.commit_group;" ::: "memory")
#define CP_WAIT(n)  asm volatile("cp.async.wait_group %0;" :: "n"(n) : "memory")

__device__ __forceinline__ void ldsm_x4(uint32_t* r, uint32_t addr) {
    asm volatile("ldmatrix.sync.aligned.m8n8.x4.shared.b16 {%0,%1,%2,%3}, [%4];"
                 : "=r"(r[0]), "=r"(r[1]), "=r"(r[2]), "=r"(r[3]) : "r"(addr));
}
__device__ __forceinline__ void ldsm_x4_t(uint32_t* r, uint32_t addr) {
    asm volatile("ldmatrix.sync.aligned.m8n8.x4.trans.shared.b16 {%0,%1,%2,%3}, [%4];"
                 : "=r"(r[0]), "=r"(r[1]), "=r"(r[2]), "=r"(r[3]) : "r"(addr));
}
// fp16 m16n8k16 mma, fp32 accum in-place
__device__ __forceinline__ void mma16(float* c, const uint32_t* a, uint32_t b0, uint32_t b1) {
    asm volatile(
        "mma.sync.aligned.m16n8k16.row.col.f32.f16.f16.f32 "
        "{%0,%1,%2,%3}, {%4,%5,%6,%7}, {%8,%9}, {%0,%1,%2,%3};"
        : "+f"(c[0]), "+f"(c[1]), "+f"(c[2]), "+f"(c[3])
        : "r"(a[0]), "r"(a[1]), "r"(a[2]), "r"(a[3]), "r"(b0), "r"(b1));
}
// ldmatrix address: lanes 0-15 -> rows r0..r0+15 @ c0b; lanes 16-31 -> same rows @ c0b+16
__device__ __forceinline__ uint32_t ldsm_addr(uint32_t base, int r0, int c0b,
                                              int rowb, int lane) {
    return base + (uint32_t)(r0 + (lane & 15)) * rowb + c0b + ((lane >> 4) << 4);
}

// ---------------------------------------------------------------------------
// fp32 -> fp16 convert (pre-pass)
// ---------------------------------------------------------------------------
__global__ void conv_fp16(const float4* __restrict__ src, __half2* __restrict__ dst, int n4)
{
    int i = blockIdx.x * blockDim.x + threadIdx.x;
    if (i < n4) {
        float4 v = src[i];
        dst[2*i]   = __floats2half2_rn(v.x, v.y);
        dst[2*i+1] = __floats2half2_rn(v.z, v.w);
    }
}

// ---------------------------------------------------------------------------
// Projection GEMM, fp16 HMMA: Out_z = X @ W_z. Tile 128x128, K-step 64, 2-stage cp.async.
// Q output pre-scaled by log2(e)/8 so attention can use raw ex2.
// ---------------------------------------------------------------------------
#define PA_ROWB 144   // 72 halves
#define PB_ROWB 272   // 136 halves
#define PA_STAGE 18432
#define PB_STAGE 17408
#define PROJ_SMEM (2*PA_STAGE + 2*PB_STAGE)   // 71680

__global__ __launch_bounds__(256, 1) void proj16_kernel()
{
    extern __shared__ char sm[];
    const uint32_t sb = smem_u32(sm);
    const uint32_t Ab = sb, Bb_ = sb + 2*PA_STAGE;

    const int tid = threadIdx.x, wid = tid >> 5, lane = tid & 31;
    const int g = lane >> 2, tig = lane & 3;
    const int wm = wid & 3, wn = wid >> 2;

    const int z  = blockIdx.z;
    const int n0 = blockIdx.x * 128;
    const int m0 = blockIdx.y * 128;
    const __half* Xp = g_X16 + (size_t)m0 * Dd;
    const __half* Wp = g_W16 + (size_t)z * Dd * Dd + n0;
    __half* Out = (z == 0) ? g_Q16 : (z == 1 ? g_K16 : g_V16);
    const float osc = (z == 0) ? 0.18033688f : 1.0f;   // log2(e)/8 folded into Q

    float C[2][8][4];
    #pragma unroll
    for (int mf = 0; mf < 2; mf++)
        #pragma unroll
        for (int nf = 0; nf < 8; nf++)
            #pragma unroll
            for (int r = 0; r < 4; r++) C[mf][nf][r] = 0.f;

    auto stage = [&](int kt, int buf) {
        const int k0 = kt * 64;
        #pragma unroll
        for (int i = 0; i < 4; i++) {           // A: 1024 16B chunks
            int ci = tid + 256 * i;
            int row = ci >> 3, seg = ci & 7;
            CP_ASYNC(Ab + buf * PA_STAGE + row * PA_ROWB + seg * 16,
                     Xp + (size_t)row * Dd + k0 + seg * 8);
        }
        #pragma unroll
        for (int i = 0; i < 4; i++) {           // B: 1024 16B chunks
            int ci = tid + 256 * i;
            int row = ci >> 4, seg = ci & 15;
            CP_ASYNC(Bb_ + buf * PB_STAGE + row * PB_ROWB + seg * 16,
                     Wp + (size_t)(k0 + row) * Dd + seg * 8);
        }
        CP_COMMIT();
    };

    stage(0, 0);
    for (int kt = 0; kt < 16; kt++) {
        if (kt < 15) { stage(kt + 1, (kt + 1) & 1); CP_WAIT(1); }
        else         { CP_WAIT(0); }
        __syncthreads();

        const uint32_t ab = Ab + (kt & 1) * PA_STAGE;
        const uint32_t bbuf = Bb_ + (kt & 1) * PB_STAGE;
        #pragma unroll
        for (int k16 = 0; k16 < 4; k16++) {
            uint32_t a[2][4];
            #pragma unroll
            for (int mf = 0; mf < 2; mf++)
                ldsm_x4(a[mf], ldsm_addr(ab, wm * 32 + mf * 16, k16 * 32, PA_ROWB, lane));
            #pragma unroll
            for (int nfp = 0; nfp < 4; nfp++) {
                uint32_t r[4];
                ldsm_x4_t(r, ldsm_addr(bbuf, k16 * 16, (wn * 64 + nfp * 16) * 2, PB_ROWB, lane));
                #pragma unroll
                for (int mf = 0; mf < 2; mf++) {
                    mma16(C[mf][2*nfp],     a[mf], r[0], r[1]);
                    mma16(C[mf][2*nfp + 1], a[mf], r[2], r[3]);
                }
            }
        }
        __syncthreads();
    }

    // epilogue: head-major fp16 scatter (Q pre-scaled)
    const int h = (n0 >> 6) + wn;
    #pragma unroll
    for (int mf = 0; mf < 2; mf++) {
        int m = m0 + wm * 32 + mf * 16 + g;
        int bidx = m >> 10, s = m & 1023;
        __half* base  = Out + ((size_t)(bidx * Hh + h) * Ss + s) * HDd;
        __half* base2 = base + 8 * HDd;
        #pragma unroll
        for (int nf = 0; nf < 8; nf++) {
            int d = nf * 8 + 2 * tig;
            *(__half2*)(base + d)  = __floats2half2_rn(C[mf][nf][0]*osc, C[mf][nf][1]*osc);
            *(__half2*)(base2 + d) = __floats2half2_rn(C[mf][nf][2]*osc, C[mf][nf][3]*osc);
        }
    }
}

// ---------------------------------------------------------------------------
// Attention, fp16 HMMA (R5 structure): CTA = 256 q-rows x (b,h); 8 warps, m32 each.
// K/V staged fp16 (2-stage cp.async), Q staged once. Softmax: raw ex2 (Q prescaled),
// fp16 mask loads (half the bytes), fp32 rowsum.
// ---------------------------------------------------------------------------
#define A_ROWB 144                 // 72 halves
#define AQ_BYTES (256*A_ROWB)      // 36864
#define AKV_BYTES (64*A_ROWB)      // 9216
#define ATTN_SMEM (AQ_BYTES + 4*AKV_BYTES)   // 73728

__global__ __launch_bounds__(256, 1) void attn16_kernel(float* __restrict__ out)
{
    extern __shared__ char sm[];
    const uint32_t sb = smem_u32(sm);
    const uint32_t Qb = sb, Kb = sb + AQ_BYTES, Vb = Kb + 2*AKV_BYTES;

    const int tid = threadIdx.x, w = tid >> 5, lane = tid & 31;
    const int g = lane >> 2, tig = lane & 3;
    const int bh = blockIdx.y, b = bh >> 4, h = bh & 15;
    const int q0 = blockIdx.x * 256;
    const int i0 = w * 32;

    const __half* Qg = g_Q16 + (size_t)bh * Ss * HDd + (size_t)q0 * HDd;
    const __half* Kg = g_K16 + (size_t)bh * Ss * HDd;
    const __half* Vg = g_V16 + (size_t)bh * Ss * HDd;
    const __half* mbase = g_M16 + ((size_t)b * Ss + q0 + i0) * Ss;

    auto stageKV = [&](int t0, int buf) {
        #pragma unroll
        for (int i = 0; i < 2; i++) {          // K
            int ci = tid + 256 * i;
            int row = ci >> 3, seg = ci & 7;
            CP_ASYNC(Kb + buf * AKV_BYTES + row * A_ROWB + seg * 16,
                     Kg + (size_t)(t0 + row) * HDd + seg * 8);
        }
        #pragma unroll
        for (int i = 0; i < 2; i++) {          // V
            int ci = tid + 256 * i;
            int row = ci >> 3, seg = ci & 7;
            CP_ASYNC(Vb + buf * AKV_BYTES + row * A_ROWB + seg * 16,
                     Vg + (size_t)(t0 + row) * HDd + seg * 8);
        }
        CP_COMMIT();
    };

    // prologue: Q (2048 chunks) + KV tile 0
    #pragma unroll
    for (int i = 0; i < 8; i++) {
        int ci = tid + 256 * i;
        int row = ci >> 3, seg = ci & 7;
        CP_ASYNC(Qb + row * A_ROWB + seg * 16, Qg + (size_t)row * HDd + seg * 8);
    }
    stageKV(0, 0);
    CP_WAIT(0);
    __syncthreads();

    uint32_t qf[2][4][4];
    #pragma unroll
    for (int mf = 0; mf < 2; mf++)
        #pragma unroll
        for (int k16 = 0; k16 < 4; k16++)
            ldsm_x4(qf[mf][k16], ldsm_addr(Qb, i0 + mf * 16, k16 * 32, A_ROWB, lane));

    float O[2][8][4];
    #pragma unroll
    for (int mf = 0; mf < 2; mf++)
        #pragma unroll
        for (int nf = 0; nf < 8; nf++)
            #pragma unroll
            for (int r = 0; r < 4; r++) O[mf][nf][r] = 0.f;
    float rs[2][2] = {{0.f, 0.f}, {0.f, 0.f}};

    for (int t = 0; t < 16; t++) {
        const int t0 = t * 64, buf = t & 1;
        if (t < 15) { stageKV(t0 + 64, buf ^ 1); CP_WAIT(1); }
        else        { CP_WAIT(0); }
        __syncthreads();

        // S = Q K^T  (S already in log2 units; Q prescaled)
        float S[2][8][4];
        #pragma unroll
        for (int mf = 0; mf < 2; mf++)
            #pragma unroll
            for (int nf = 0; nf < 8; nf++)
                #pragma unroll
                for (int r = 0; r < 4; r++) S[mf][nf][r] = 0.f;
        const uint32_t kb = Kb + buf * AKV_BYTES;
        #pragma unroll
        for (int k16 = 0; k16 < 4; k16++) {
            #pragma unroll
            for (int nfp = 0; nfp < 4; nfp++) {
                uint32_t r[4];
                ldsm_x4(r, ldsm_addr(kb, nfp * 16, k16 * 32, A_ROWB, lane));
                #pragma unroll
                for (int mf = 0; mf < 2; mf++) {
                    mma16(S[mf][2*nfp],     qf[mf][k16], r[0], r[2]);
                    mma16(S[mf][2*nfp + 1], qf[mf][k16], r[1], r[3]);
                }
            }
        }

        // P = ex2(S) * mask (fp16 mask loads), packed fp16; rowsum fp32
        uint32_t Pp[2][8][2];
        #pragma unroll
        for (int mf = 0; mf < 2; mf++) {
            #pragma unroll
            for (int nf = 0; nf < 8; nf++) {
                const __half* mp = mbase + (size_t)(mf * 16 + g) * Ss + t0 + nf * 8 + 2 * tig;
                float2 m01 = __half22float2(*(const __half2*)mp);
                float2 m23 = __half22float2(*(const __half2*)(mp + 8 * Ss));
                float e0 = ex2f(S[mf][nf][0]) * m01.x;
                float e1 = ex2f(S[mf][nf][1]) * m01.y;
                float e2 = ex2f(S[mf][nf][2]) * m23.x;
                float e3 = ex2f(S[mf][nf][3]) * m23.y;
                rs[mf][0] += e0 + e1;
                rs[mf][1] += e2 + e3;
                Pp[mf][nf][0] = h2u(__floats2half2_rn(e0, e1));
                Pp[mf][nf][1] = h2u(__floats2half2_rn(e2, e3));
            }
        }

        // O += P V
        const uint32_t vb = Vb + buf * AKV_BYTES;
        #pragma unroll
        for (int kt = 0; kt < 4; kt++) {
            #pragma unroll
            for (int nfp = 0; nfp < 4; nfp++) {
                uint32_t r[4];
                ldsm_x4_t(r, ldsm_addr(vb, kt * 16, nfp * 32, A_ROWB, lane));
                #pragma unroll
                for (int mf = 0; mf < 2; mf++) {
                    uint32_t a[4] = { Pp[mf][2*kt][0], Pp[mf][2*kt][1],
                                      Pp[mf][2*kt + 1][0], Pp[mf][2*kt + 1][1] };
                    mma16(O[mf][2*nfp],     a, r[0], r[1]);
                    mma16(O[mf][2*nfp + 1], a, r[2], r[3]);
                }
            }
        }
        __syncthreads();
    }

    // normalize + store
    #pragma unroll
    for (int mf = 0; mf < 2; mf++) {
        float r0 = rs[mf][0], r1 = rs[mf][1];
        r0 += __shfl_xor_sync(0xffffffffu, r0, 1);
        r0 += __shfl_xor_sync(0xffffffffu, r0, 2);
        r1 += __shfl_xor_sync(0xffffffffu, r1, 1);
        r1 += __shfl_xor_sync(0xffffffffu, r1, 2);
        const float inv0 = 1.0f / (r0 + 1e-8f);
        const float inv1 = 1.0f / (r1 + 1e-8f);
        float* o0 = out + ((size_t)b * Ss + q0 + i0 + mf * 16 + g) * Dd + h * HDd;
        float* o1 = o0 + 8 * Dd;
        #pragma unroll
        for (int nf = 0; nf < 8; nf++) {
            int d = nf * 8 + 2 * tig;
            *(float2*)(o0 + d) = make_float2(O[mf][nf][0] * inv0, O[mf][nf][1] * inv0);
            *(float2*)(o1 + d) = make_float2(O[mf][nf][2] * inv1, O[mf][nf][3] * inv1);
        }
    }
}

// ---------------------------------------------------------------------------
extern "C" void kernel_launch(void* const* d_in, const int* in_sizes, int n_in,
                              void* d_out, int out_size)
{
    const float* x    = (const float*)d_in[0];
    const float* mask = (const float*)d_in[1];
    const float* Wq   = (const float*)d_in[2];
    const float* Wk   = (const float*)d_in[3];
    const float* Wv   = (const float*)d_in[4];
    float* out = (float*)d_out;

    __half* gX; cudaGetSymbolAddress((void**)&gX, g_X16);
    __half* gW; cudaGetSymbolAddress((void**)&gW, g_W16);
    __half* gM; cudaGetSymbolAddress((void**)&gM, g_M16);

    // 1) fp32 -> fp16 pre-pass (x, weights, mask)
    const int n4x = Mtot * Dd / 4;
    const int n4w = Dd * Dd / 4;
    const int n4m = Bb * Ss * Ss / 4;
    conv_fp16<<<(n4x + 255) / 256, 256>>>((const float4*)x, (__half2*)gX, n4x);
    conv_fp16<<<(n4w + 255) / 256, 256>>>((const float4*)Wq, (__half2*)gW, n4w);
    conv_fp16<<<(n4w + 255) / 256, 256>>>((const float4*)Wk, (__half2*)(gW + (size_t)Dd*Dd), n4w);
    conv_fp16<<<(n4w + 255) / 256, 256>>>((const float4*)Wv, (__half2*)(gW + (size_t)2*Dd*Dd), n4w);
    conv_fp16<<<(n4m + 255) / 256, 256>>>((const float4*)mask, (__half2*)gM, n4m);

    // 2) projections (fp16 HMMA)
    cudaFuncSetAttribute(proj16_kernel, cudaFuncAttributeMaxDynamicSharedMemorySize,
                         PROJ_SMEM);
    dim3 pgrid(Dd / 128, Mtot / 128, 3);
    proj16_kernel<<<pgrid, 256, PROJ_SMEM>>>();

    // 3) attention (fp16 HMMA)
    cudaFuncSetAttribute(attn16_kernel, cudaFuncAttributeMaxDynamicSharedMemorySize,
                         ATTN_SMEM);
    dim3 agrid(Ss / 256, BHh);
    attn16_kernel<<<agrid, 256, ATTN_SMEM>>>(out);
}

// round 8
// speedup vs baseline: 1.1911x; 1.0242x over previous
#include <cuda_runtime.h>
#include <cuda_fp16.h>
#include <cstdint>

// Problem constants
#define Hh   16
#define Ss   1024
#define Dd   1024
#define HDd  64
#define Bb   8
#define BHh  (Bb*Hh)      // 128
#define Mtot (Bb*Ss)      // 8192

// fp16 scratch (device globals; no allocation allowed)
__device__ __half g_X16[(size_t)Mtot*Dd];
__device__ __half g_W16[(size_t)3*Dd*Dd];
__device__ __half g_M16[(size_t)Bb*Ss*Ss];         // fp16 mask (0/1 exact)
__device__ __half g_Q16[(size_t)BHh*Ss*HDd];       // head-major, pre-scaled by log2e/8
__device__ __half g_K16[(size_t)BHh*Ss*HDd];
__device__ __half g_V16[(size_t)BHh*Ss*HDd];

// ---------------------------------------------------------------------------
__device__ __forceinline__ uint32_t h2u(__half2 h) {
    union { __half2 h; uint32_t u; } c; c.h = h; return c.u;
}
__device__ __forceinline__ float ex2f(float x) {
    float y; asm("ex2.approx.f32 %0, %1;" : "=f"(y) : "f"(x)); return y;
}
__device__ __forceinline__ uint32_t smem_u32(const void* p) {
    uint32_t a;
    asm("{ .reg .u64 t; cvta.to.shared.u64 t, %1; cvt.u32.u64 %0, t; }" : "=r"(a) : "l"(p));
    return a;
}
#define CP_ASYNC(dst, src) \
    asm volatile("cp.async.ca.shared.global [%0], [%1], 16;" :: "r"(dst), "l"(src) : "memory")
#define CP_COMMIT() asm volatile("cp.async.commit_group;" ::: "memory")
#define CP_WAIT(n)  asm volatile("cp.async.wait_group %0;" :: "n"(n) : "memory")

__device__ __forceinline__ void ldsm_x4(uint32_t* r, uint32_t addr) {
    asm volatile("ldmatrix.sync.aligned.m8n8.x4.shared.b16 {%0,%1,%2,%3}, [%4];"
                 : "=r"(r[0]), "=r"(r[1]), "=r"(r[2]), "=r"(r[3]) : "r"(addr));
}
__device__ __forceinline__ void ldsm_x4_t(uint32_t* r, uint32_t addr) {
    asm volatile("ldmatrix.sync.aligned.m8n8.x4.trans.shared.b16 {%0,%1,%2,%3}, [%4];"
                 : "=r"(r[0]), "=r"(r[1]), "=r"(r[2]), "=r"(r[3]) : "r"(addr));
}
// fp16 m16n8k16 mma, fp32 accum in-place
__device__ __forceinline__ void mma16(float* c, const uint32_t* a, uint32_t b0, uint32_t b1) {
    asm volatile(
        "mma.sync.aligned.m16n8k16.row.col.f32.f16.f16.f32 "
        "{%0,%1,%2,%3}, {%4,%5,%6,%7}, {%8,%9}, {%0,%1,%2,%3};"
        : "+f"(c[0]), "+f"(c[1]), "+f"(c[2]), "+f"(c[3])
        : "r"(a[0]), "r"(a[1]), "r"(a[2]), "r"(a[3]), "r"(b0), "r"(b1));
}
__device__ __forceinline__ uint32_t ldsm_addr(uint32_t base, int r0, int c0b,
                                              int rowb, int lane) {
    return base + (uint32_t)(r0 + (lane & 15)) * rowb + c0b + ((lane >> 4) << 4);
}

// ---------------------------------------------------------------------------
// fp32 -> fp16 convert pre-passes
// ---------------------------------------------------------------------------
__global__ void conv_fp16(const float4* __restrict__ src, __half2* __restrict__ dst, int n4)
{
    int i = blockIdx.x * blockDim.x + threadIdx.x;
    if (i < n4) {
        float4 v = src[i];
        dst[2*i]   = __floats2half2_rn(v.x, v.y);
        dst[2*i+1] = __floats2half2_rn(v.z, v.w);
    }
}
__global__ void conv_w3(const float4* __restrict__ Wq, const float4* __restrict__ Wk,
                        const float4* __restrict__ Wv, int n4)
{
    int i = blockIdx.x * blockDim.x + threadIdx.x;
    const float4* src = (blockIdx.z == 0) ? Wq : (blockIdx.z == 1 ? Wk : Wv);
    __half2* dst = (__half2*)(g_W16 + (size_t)blockIdx.z * Dd * Dd);
    if (i < n4) {
        float4 v = src[i];
        dst[2*i]   = __floats2half2_rn(v.x, v.y);
        dst[2*i+1] = __floats2half2_rn(v.z, v.w);
    }
}

// ---------------------------------------------------------------------------
// Projection GEMM, fp16 HMMA (unchanged from R7): tile 128x128, K-step 64.
// Q output pre-scaled by log2(e)/8.
// ---------------------------------------------------------------------------
#define PA_ROWB 144
#define PB_ROWB 272
#define PA_STAGE 18432
#define PB_STAGE 17408
#define PROJ_SMEM (2*PA_STAGE + 2*PB_STAGE)   // 71680

__global__ __launch_bounds__(256, 1) void proj16_kernel()
{
    extern __shared__ char sm[];
    const uint32_t sb = smem_u32(sm);
    const uint32_t Ab = sb, Bb_ = sb + 2*PA_STAGE;

    const int tid = threadIdx.x, wid = tid >> 5, lane = tid & 31;
    const int g = lane >> 2, tig = lane & 3;
    const int wm = wid & 3, wn = wid >> 2;

    const int z  = blockIdx.z;
    const int n0 = blockIdx.x * 128;
    const int m0 = blockIdx.y * 128;
    const __half* Xp = g_X16 + (size_t)m0 * Dd;
    const __half* Wp = g_W16 + (size_t)z * Dd * Dd + n0;
    __half* Out = (z == 0) ? g_Q16 : (z == 1 ? g_K16 : g_V16);
    const float osc = (z == 0) ? 0.18033688f : 1.0f;   // log2(e)/8 folded into Q

    float C[2][8][4];
    #pragma unroll
    for (int mf = 0; mf < 2; mf++)
        #pragma unroll
        for (int nf = 0; nf < 8; nf++)
            #pragma unroll
            for (int r = 0; r < 4; r++) C[mf][nf][r] = 0.f;

    auto stage = [&](int kt, int buf) {
        const int k0 = kt * 64;
        #pragma unroll
        for (int i = 0; i < 4; i++) {
            int ci = tid + 256 * i;
            int row = ci >> 3, seg = ci & 7;
            CP_ASYNC(Ab + buf * PA_STAGE + row * PA_ROWB + seg * 16,
                     Xp + (size_t)row * Dd + k0 + seg * 8);
        }
        #pragma unroll
        for (int i = 0; i < 4; i++) {
            int ci = tid + 256 * i;
            int row = ci >> 4, seg = ci & 15;
            CP_ASYNC(Bb_ + buf * PB_STAGE + row * PB_ROWB + seg * 16,
                     Wp + (size_t)(k0 + row) * Dd + seg * 8);
        }
        CP_COMMIT();
    };

    stage(0, 0);
    for (int kt = 0; kt < 16; kt++) {
        if (kt < 15) { stage(kt + 1, (kt + 1) & 1); CP_WAIT(1); }
        else         { CP_WAIT(0); }
        __syncthreads();

        const uint32_t ab = Ab + (kt & 1) * PA_STAGE;
        const uint32_t bbuf = Bb_ + (kt & 1) * PB_STAGE;
        #pragma unroll
        for (int k16 = 0; k16 < 4; k16++) {
            uint32_t a[2][4];
            #pragma unroll
            for (int mf = 0; mf < 2; mf++)
                ldsm_x4(a[mf], ldsm_addr(ab, wm * 32 + mf * 16, k16 * 32, PA_ROWB, lane));
            #pragma unroll
            for (int nfp = 0; nfp < 4; nfp++) {
                uint32_t r[4];
                ldsm_x4_t(r, ldsm_addr(bbuf, k16 * 16, (wn * 64 + nfp * 16) * 2, PB_ROWB, lane));
                #pragma unroll
                for (int mf = 0; mf < 2; mf++) {
                    mma16(C[mf][2*nfp],     a[mf], r[0], r[1]);
                    mma16(C[mf][2*nfp + 1], a[mf], r[2], r[3]);
                }
            }
        }
        __syncthreads();
    }

    const int h = (n0 >> 6) + wn;
    #pragma unroll
    for (int mf = 0; mf < 2; mf++) {
        int m = m0 + wm * 32 + mf * 16 + g;
        int bidx = m >> 10, s = m & 1023;
        __half* base  = Out + ((size_t)(bidx * Hh + h) * Ss + s) * HDd;
        __half* base2 = base + 8 * HDd;
        #pragma unroll
        for (int nf = 0; nf < 8; nf++) {
            int d = nf * 8 + 2 * tig;
            *(__half2*)(base + d)  = __floats2half2_rn(C[mf][nf][0]*osc, C[mf][nf][1]*osc);
            *(__half2*)(base2 + d) = __floats2half2_rn(C[mf][nf][2]*osc, C[mf][nf][3]*osc);
        }
    }
}

// ---------------------------------------------------------------------------
// Attention, fp16 HMMA, occupancy 2: CTA = 128 q-rows x (b,h); 8 warps, m16 each.
// Per-thread state ~96 arch regs -> fits 128-reg occ-2 cap without spills.
// Structure otherwise identical to R7 (full-tile S -> softmax -> PV).
// ---------------------------------------------------------------------------
#define A_ROWB 144                 // 72 halves
#define AQ_BYTES (128*A_ROWB)      // 18432
#define AKV_BYTES (64*A_ROWB)      // 9216
#define ATTN_SMEM (AQ_BYTES + 4*AKV_BYTES)   // 55296

__global__ __launch_bounds__(256, 2) void attn16_kernel(float* __restrict__ out)
{
    extern __shared__ char sm[];
    const uint32_t sb = smem_u32(sm);
    const uint32_t Qb = sb, Kb = sb + AQ_BYTES, Vb = Kb + 2*AKV_BYTES;

    const int tid = threadIdx.x, w = tid >> 5, lane = tid & 31;
    const int g = lane >> 2, tig = lane & 3;
    const int bh = blockIdx.y, b = bh >> 4, h = bh & 15;
    const int q0 = blockIdx.x * 128;
    const int i0 = w * 16;

    const __half* Qg = g_Q16 + (size_t)bh * Ss * HDd + (size_t)q0 * HDd;
    const __half* Kg = g_K16 + (size_t)bh * Ss * HDd;
    const __half* Vg = g_V16 + (size_t)bh * Ss * HDd;
    const __half* mbase = g_M16 + ((size_t)b * Ss + q0 + i0) * Ss;

    auto stageKV = [&](int t0, int buf) {
        #pragma unroll
        for (int i = 0; i < 2; i++) {          // K
            int ci = tid + 256 * i;
            int row = ci >> 3, seg = ci & 7;
            CP_ASYNC(Kb + buf * AKV_BYTES + row * A_ROWB + seg * 16,
                     Kg + (size_t)(t0 + row) * HDd + seg * 8);
        }
        #pragma unroll
        for (int i = 0; i < 2; i++) {          // V
            int ci = tid + 256 * i;
            int row = ci >> 3, seg = ci & 7;
            CP_ASYNC(Vb + buf * AKV_BYTES + row * A_ROWB + seg * 16,
                     Vg + (size_t)(t0 + row) * HDd + seg * 8);
        }
        CP_COMMIT();
    };

    // prologue: Q (1024 chunks) + KV tile 0
    #pragma unroll
    for (int i = 0; i < 4; i++) {
        int ci = tid + 256 * i;
        int row = ci >> 3, seg = ci & 7;
        CP_ASYNC(Qb + row * A_ROWB + seg * 16, Qg + (size_t)row * HDd + seg * 8);
    }
    stageKV(0, 0);
    CP_WAIT(0);
    __syncthreads();

    uint32_t qf[4][4];
    #pragma unroll
    for (int k16 = 0; k16 < 4; k16++)
        ldsm_x4(qf[k16], ldsm_addr(Qb, i0, k16 * 32, A_ROWB, lane));

    float O[8][4];
    #pragma unroll
    for (int nf = 0; nf < 8; nf++)
        #pragma unroll
        for (int r = 0; r < 4; r++) O[nf][r] = 0.f;
    float rs0 = 0.f, rs1 = 0.f;

    for (int t = 0; t < 16; t++) {
        const int t0 = t * 64, buf = t & 1;
        if (t < 15) { stageKV(t0 + 64, buf ^ 1); CP_WAIT(1); }
        else        { CP_WAIT(0); }
        __syncthreads();

        // S = Q K^T (log2 units; Q prescaled)
        float S[8][4];
        #pragma unroll
        for (int nf = 0; nf < 8; nf++)
            #pragma unroll
            for (int r = 0; r < 4; r++) S[nf][r] = 0.f;
        const uint32_t kb = Kb + buf * AKV_BYTES;
        #pragma unroll
        for (int k16 = 0; k16 < 4; k16++) {
            #pragma unroll
            for (int nfp = 0; nfp < 4; nfp++) {
                uint32_t r[4];
                ldsm_x4(r, ldsm_addr(kb, nfp * 16, k16 * 32, A_ROWB, lane));
                mma16(S[2*nfp],     qf[k16], r[0], r[2]);
                mma16(S[2*nfp + 1], qf[k16], r[1], r[3]);
            }
        }

        // P = ex2(S) * mask (fp16 mask loads), packed fp16; rowsum fp32
        uint32_t Pp[8][2];
        #pragma unroll
        for (int nf = 0; nf < 8; nf++) {
            const __half* mp = mbase + (size_t)g * Ss + t0 + nf * 8 + 2 * tig;
            float2 m01 = __half22float2(*(const __half2*)mp);
            float2 m23 = __half22float2(*(const __half2*)(mp + 8 * Ss));
            float e0 = ex2f(S[nf][0]) * m01.x;
            float e1 = ex2f(S[nf][1]) * m01.y;
            float e2 = ex2f(S[nf][2]) * m23.x;
            float e3 = ex2f(S[nf][3]) * m23.y;
            rs0 += e0 + e1;
            rs1 += e2 + e3;
            Pp[nf][0] = h2u(__floats2half2_rn(e0, e1));
            Pp[nf][1] = h2u(__floats2half2_rn(e2, e3));
        }

        // O += P V
        const uint32_t vb = Vb + buf * AKV_BYTES;
        #pragma unroll
        for (int kt = 0; kt < 4; kt++) {
            #pragma unroll
            for (int nfp = 0; nfp < 4; nfp++) {
                uint32_t r[4];
                ldsm_x4_t(r, ldsm_addr(vb, kt * 16, nfp * 32, A_ROWB, lane));
                uint32_t a[4] = { Pp[2*kt][0], Pp[2*kt][1],
                                  Pp[2*kt + 1][0], Pp[2*kt + 1][1] };
                mma16(O[2*nfp],     a, r[0], r[1]);
                mma16(O[2*nfp + 1], a, r[2], r[3]);
            }
        }
        __syncthreads();
    }

    // normalize + store
    rs0 += __shfl_xor_sync(0xffffffffu, rs0, 1);
    rs0 += __shfl_xor_sync(0xffffffffu, rs0, 2);
    rs1 += __shfl_xor_sync(0xffffffffu, rs1, 1);
    rs1 += __shfl_xor_sync(0xffffffffu, rs1, 2);
    const float inv0 = 1.0f / (rs0 + 1e-8f);
    const float inv1 = 1.0f / (rs1 + 1e-8f);
    float* o0 = out + ((size_t)b * Ss + q0 + i0 + g) * Dd + h * HDd;
    float* o1 = o0 + 8 * Dd;
    #pragma unroll
    for (int nf = 0; nf < 8; nf++) {
        int d = nf * 8 + 2 * tig;
        *(float2*)(o0 + d) = make_float2(O[nf][0] * inv0, O[nf][1] * inv0);
        *(float2*)(o1 + d) = make_float2(O[nf][2] * inv1, O[nf][3] * inv1);
    }
}

// ---------------------------------------------------------------------------
extern "C" void kernel_launch(void* const* d_in, const int* in_sizes, int n_in,
                              void* d_out, int out_size)
{
    const float* x    = (const float*)d_in[0];
    const float* mask = (const float*)d_in[1];
    const float* Wq   = (const float*)d_in[2];
    const float* Wk   = (const float*)d_in[3];
    const float* Wv   = (const float*)d_in[4];
    float* out = (float*)d_out;

    __half* gX; cudaGetSymbolAddress((void**)&gX, g_X16);
    __half* gM; cudaGetSymbolAddress((void**)&gM, g_M16);

    // 1) fp32 -> fp16 pre-pass (x, weights, mask)
    const int n4x = Mtot * Dd / 4;
    const int n4w = Dd * Dd / 4;
    const int n4m = Bb * Ss * Ss / 4;
    conv_fp16<<<(n4x + 255) / 256, 256>>>((const float4*)x, (__half2*)gX, n4x);
    {
        dim3 wgrid((n4w + 255) / 256, 1, 3);
        conv_w3<<<wgrid, 256>>>((const float4*)Wq, (const float4*)Wk,
                                (const float4*)Wv, n4w);
    }
    conv_fp16<<<(n4m + 255) / 256, 256>>>((const float4*)mask, (__half2*)gM, n4m);

    // 2) projections (fp16 HMMA)
    cudaFuncSetAttribute(proj16_kernel, cudaFuncAttributeMaxDynamicSharedMemorySize,
                         PROJ_SMEM);
    dim3 pgrid(Dd / 128, Mtot / 128, 3);
    proj16_kernel<<<pgrid, 256, PROJ_SMEM>>>();

    // 3) attention (fp16 HMMA, occ 2)
    cudaFuncSetAttribute(attn16_kernel, cudaFuncAttributeMaxDynamicSharedMemorySize,
                         ATTN_SMEM);
    dim3 agrid(Ss / 128, BHh);              // (8, 128)
    attn16_kernel<<<agrid, 256, ATTN_SMEM>>>(out);
}